// round 2
// baseline (speedup 1.0000x reference)
#include <cuda_runtime.h>
#include <math_constants.h>

#define IMG_H 1024
#define IMG_W 1024
#define IMG   (IMG_H * IMG_W)
#define NIMG  16          // batch images
#define NF    32          // 32 fields: [0..15] = probs (pred), [16..31] = target (gt)
#define TS    32          // tile size

// Scratch: static device globals (no dynamic allocation allowed).
__device__ float  g_bufA[(size_t)NF * IMG];   // 128 MB
__device__ float  g_bufB[(size_t)NF * IMG];   // 128 MB
__device__ double g_acc[2 * NIMG];            // tp[0..15], ts[16..31]

// ---------------------------------------------------------------------------
// init: bufA[0..15] = sigmoid(logits); bufA[16..31] = (float)target.
// Also zeroes the accumulators (must happen on every graph replay).
// ---------------------------------------------------------------------------
__global__ void init_kernel(const float4* __restrict__ logits,
                            const int4*   __restrict__ target)
{
    if (blockIdx.x == 0 && threadIdx.x < 2 * NIMG) g_acc[threadIdx.x] = 0.0;

    const int n4 = NIMG * IMG / 4;
    float4* a4 = reinterpret_cast<float4*>(g_bufA);
    for (int i = blockIdx.x * blockDim.x + threadIdx.x; i < n4;
         i += gridDim.x * blockDim.x) {
        float4 l = logits[i];
        float4 p;
        p.x = 1.f / (1.f + __expf(-l.x));
        p.y = 1.f / (1.f + __expf(-l.y));
        p.z = 1.f / (1.f + __expf(-l.z));
        p.w = 1.f / (1.f + __expf(-l.w));
        a4[i] = p;
        int4 t = target[i];
        float4 tf;
        tf.x = (float)t.x; tf.y = (float)t.y; tf.z = (float)t.z; tf.w = (float)t.w;
        a4[n4 + i] = tf;
    }
}

// ---------------------------------------------------------------------------
// One soft-skeleton iteration, fully fused:
//   eroded = minpool3(x)   (SAME pad, +inf)
//   opened = maxpool3(eroded) (SAME pad, -inf)
//   x' = clip(x - (opened - eroded), 0, 1)
// Shared-memory tile 32x32 with halo 2.
// ---------------------------------------------------------------------------
__global__ void __launch_bounds__(1024)
iter_kernel(const float* __restrict__ src, float* __restrict__ dst)
{
    __shared__ float xs[TS + 4][TS + 5];   // x with halo 2
    __shared__ float es[TS + 2][TS + 3];   // eroded with halo 1

    const int z  = blockIdx.z;
    const int ox = blockIdx.x * TS;
    const int oy = blockIdx.y * TS;
    const float* s = src + (size_t)z * IMG;
    float*       d = dst + (size_t)z * IMG;
    const int tid = threadIdx.x;

    // Load x tile + halo; out-of-image -> +inf (min-pool padding)
    for (int i = tid; i < (TS + 4) * (TS + 4); i += 1024) {
        int ly = i / (TS + 4), lx = i % (TS + 4);
        int gy = oy + ly - 2,  gx = ox + lx - 2;
        float v = CUDART_INF_F;
        if ((unsigned)gy < IMG_H && (unsigned)gx < IMG_W)
            v = __ldg(&s[gy * IMG_W + gx]);
        xs[ly][lx] = v;
    }
    __syncthreads();

    // Erosion on tile + halo 1; out-of-image positions forced to -inf
    // (that's the max-pool's own SAME padding of the eroded array).
    for (int i = tid; i < (TS + 2) * (TS + 2); i += 1024) {
        int ly = i / (TS + 2), lx = i % (TS + 2);
        int gy = oy + ly - 1,  gx = ox + lx - 1;
        float e = -CUDART_INF_F;
        if ((unsigned)gy < IMG_H && (unsigned)gx < IMG_W) {
            e =          xs[ly    ][lx];
            e = fminf(e, xs[ly    ][lx + 1]);
            e = fminf(e, xs[ly    ][lx + 2]);
            e = fminf(e, xs[ly + 1][lx]);
            e = fminf(e, xs[ly + 1][lx + 1]);
            e = fminf(e, xs[ly + 1][lx + 2]);
            e = fminf(e, xs[ly + 2][lx]);
            e = fminf(e, xs[ly + 2][lx + 1]);
            e = fminf(e, xs[ly + 2][lx + 2]);
        }
        es[ly][lx] = e;
    }
    __syncthreads();

    // Dilation of eroded + update, one output pixel per thread
    const int tx = tid & 31, ty = tid >> 5;
    float x  = xs[ty + 2][tx + 2];
    float er = es[ty + 1][tx + 1];
    float op =          es[ty    ][tx];
    op = fmaxf(op,      es[ty    ][tx + 1]);
    op = fmaxf(op,      es[ty    ][tx + 2]);
    op = fmaxf(op,      es[ty + 1][tx]);
    op = fmaxf(op,      er);
    op = fmaxf(op,      es[ty + 1][tx + 2]);
    op = fmaxf(op,      es[ty + 2][tx]);
    op = fmaxf(op,      es[ty + 2][tx + 1]);
    op = fmaxf(op,      es[ty + 2][tx + 2]);

    float nx = x - (op - er);
    nx = fminf(fmaxf(nx, 0.f), 1.f);
    d[(oy + ty) * IMG_W + (ox + tx)] = nx;
}

// ---------------------------------------------------------------------------
// Reduction: tp[z] = sum(skel_pred * tgt), ts[z] = sum(skel_gt * sigmoid(logit))
// ---------------------------------------------------------------------------
__global__ void reduce_kernel(const float* __restrict__ skel,
                              const float* __restrict__ logits,
                              const int*   __restrict__ target)
{
    const int z = blockIdx.y;
    const float* sp = skel   + (size_t)z * IMG;           // skel_pred
    const float* sg = skel   + (size_t)(NIMG + z) * IMG;  // skel_gt
    const float* lg = logits + (size_t)z * IMG;
    const int*   tg = target + (size_t)z * IMG;

    float tp = 0.f, ts = 0.f;
    const int stride = gridDim.x * blockDim.x;
    for (int idx = blockIdx.x * blockDim.x + threadIdx.x; idx < IMG; idx += stride) {
        float t = (float)tg[idx];
        tp += sp[idx] * t;
        float pr = 1.f / (1.f + __expf(-lg[idx]));
        ts += sg[idx] * pr;
    }

    __shared__ float s1[256], s2[256];
    s1[threadIdx.x] = tp;
    s2[threadIdx.x] = ts;
    __syncthreads();
    for (int o = 128; o > 0; o >>= 1) {
        if (threadIdx.x < o) {
            s1[threadIdx.x] += s1[threadIdx.x + o];
            s2[threadIdx.x] += s2[threadIdx.x + o];
        }
        __syncthreads();
    }
    if (threadIdx.x == 0) {
        atomicAdd(&g_acc[z],        (double)s1[0]);
        atomicAdd(&g_acc[NIMG + z], (double)s2[0]);
    }
}

__global__ void final_kernel(float* __restrict__ out)
{
    const int t = threadIdx.x;
    float v = 0.f;
    if (t < NIMG) {
        double tp = g_acc[t], ts = g_acc[NIMG + t];
        double num = 2.0 * tp * ts;
        double den = tp + ts;
        double c = (den > 0.0) ? (num + 1e-6) / (den + 1e-6) : 1.0;
        c = fmin(fmax(c, 0.0), 1.0);
        v = (float)(1.0 - c);
    }
    for (int o = 16; o > 0; o >>= 1) v += __shfl_down_sync(0xffffffffu, v, o);
    if (t == 0) out[0] = v / (float)NIMG;
}

// ---------------------------------------------------------------------------
extern "C" void kernel_launch(void* const* d_in, const int* in_sizes, int n_in,
                              void* d_out, int out_size)
{
    const float* logits = (const float*)d_in[0];
    const int*   target = (const int*)d_in[1];
    float*       out    = (float*)d_out;

    float *A = nullptr, *B = nullptr;
    cudaGetSymbolAddress((void**)&A, g_bufA);
    cudaGetSymbolAddress((void**)&B, g_bufB);
    float* bufs[2] = {A, B};

    init_kernel<<<2048, 256>>>((const float4*)logits, (const int4*)target);

    dim3 grid(IMG_W / TS, IMG_H / TS, NF);
    for (int it = 0; it < 5; ++it)
        iter_kernel<<<grid, 1024>>>(bufs[it & 1], bufs[(it + 1) & 1]);

    reduce_kernel<<<dim3(256, NIMG), 256>>>(bufs[1], logits, target);
    final_kernel<<<1, 32>>>(out);
}

// round 3
// speedup vs baseline: 3.3350x; 3.3350x over previous
#include <cuda_runtime.h>
#include <math_constants.h>

#define IMG_H 1024
#define IMG_W 1024
#define IMG   (IMG_H * IMG_W)
#define NIMG  16
#define NF    32            // fields: [0..15]=pred(sigmoid), [16..31]=gt(target)
#define R     16            // output rows per lane
#define WCOLS 28            // output columns per warp (32 lanes - 2*2 halo)
#define NWARP 8             // warps per block
#define CTILES ((IMG_W + WCOLS - 1) / WCOLS)   // 37

// Scratch (static device globals; no dynamic allocation allowed)
__device__ float  g_bufA[(size_t)NF * IMG];   // 128 MB
__device__ float  g_bufB[(size_t)NF * IMG];   // 128 MB
__device__ double g_acc[NF];                  // [0..15]=tp, [16..31]=ts

__device__ __forceinline__ float sigmoidf(float x) { return 1.f / (1.f + __expf(-x)); }

// ---------------------------------------------------------------------------
// One soft-skeleton iteration, register-streaming separable min/max pools.
//   eroded = minpool3(x)      (SAME pad +inf)  -> vertical min3 + shuffle hmin3
//   opened = maxpool3(eroded) (SAME pad -inf)  -> vertical max3 + shuffle hmax3
//   x' = clip(x - (opened - eroded), 0, 1)
// MODE 0: x loaded as sigmoid(logits) / (float)target  (fused init)
// MODE 1: plain buffer -> buffer
// MODE 2: no output write; accumulate tp/ts reductions (fused epilogue)
// ---------------------------------------------------------------------------
template<int MODE>
__global__ void __launch_bounds__(NWARP * 32)
skel_kernel(const float* __restrict__ src,
            const float* __restrict__ logits,
            const int*   __restrict__ target,
            float*       __restrict__ dst)
{
    const int lane = threadIdx.x & 31;
    const int warp = threadIdx.x >> 5;
    const int z    = blockIdx.z;
    const int col  = blockIdx.x * WCOLS + lane - 2;
    const int row0 = (blockIdx.y * NWARP + warp) * R;
    const bool colok = (unsigned)col < IMG_W;

    if (MODE == 0 && blockIdx.x == 0 && blockIdx.y == 0 && blockIdx.z == 0 &&
        threadIdx.x < NF)
        g_acc[threadIdx.x] = 0.0;     // zeroed before MODE 2 runs (stream order)

    const float* sf = nullptr;
    const int*   si = nullptr;
    if (MODE == 0) {
        if (z < NIMG) sf = logits + (size_t)z * IMG;
        else          si = target + (size_t)(z - NIMG) * IMG;
    } else {
        sf = src + (size_t)z * IMG;
    }

    auto loadx = [&](int gr) -> float {
        if (!colok || (unsigned)gr >= IMG_H) return CUDART_INF_F;
        int idx = gr * IMG_W + col;
        if (MODE == 0) {
            if (z < NIMG) return sigmoidf(__ldg(&sf[idx]));
            else          return (float)__ldg(&si[idx]);
        }
        return __ldg(&sf[idx]);
    };

    float xs[R];        // original x, rows row0..row0+R-1
    float er[R + 2];    // eroded, rows row0-1..row0+R

    // Phase 1: rolling vertical min3 + horizontal min3 via shuffles
    float a = loadx(row0 - 2);
    float b = loadx(row0 - 1);
    #pragma unroll
    for (int j = 0; j <= R + 1; ++j) {
        float c = loadx(row0 + j);
        if (j < R) xs[j] = c;
        float v = fminf(a, fminf(b, c));
        float l = __shfl_up_sync(0xffffffffu, v, 1);
        float r = __shfl_down_sync(0xffffffffu, v, 1);
        float e = fminf(v, fminf(l, r));
        int gr = row0 - 1 + j;
        // out-of-image eroded positions must be -inf for the following max-pool
        er[j] = (colok && (unsigned)gr < IMG_H) ? e : -CUDART_INF_F;
        a = b; b = c;
    }

    // Phase 2: vertical max3 + horizontal max3 + update (+ optional reduction)
    float accum = 0.f;
    const bool outok = (lane >= 2) && (lane < 2 + WCOLS) && colok;
    #pragma unroll
    for (int i = 0; i < R; ++i) {
        float v = fmaxf(er[i], fmaxf(er[i + 1], er[i + 2]));
        float l = __shfl_up_sync(0xffffffffu, v, 1);
        float r = __shfl_down_sync(0xffffffffu, v, 1);
        float op = fmaxf(v, fmaxf(l, r));
        float nx = xs[i] - (op - er[i + 1]);
        nx = fminf(fmaxf(nx, 0.f), 1.f);

        if (MODE == 2) {
            if (outok) {
                int idx = (row0 + i) * IMG_W + col;
                float w = (z < NIMG)
                        ? (float)__ldg(&target[(size_t)z * IMG + idx])
                        : sigmoidf(__ldg(&logits[(size_t)(z - NIMG) * IMG + idx]));
                accum += nx * w;
            }
        } else {
            if (outok)
                dst[(size_t)z * IMG + (row0 + i) * IMG_W + col] = nx;
        }
    }

    if (MODE == 2) {
        #pragma unroll
        for (int o = 16; o > 0; o >>= 1)
            accum += __shfl_down_sync(0xffffffffu, accum, o);
        __shared__ float sacc[NWARP];
        if (lane == 0) sacc[warp] = accum;
        __syncthreads();
        if (threadIdx.x == 0) {
            float t = 0.f;
            #pragma unroll
            for (int i = 0; i < NWARP; ++i) t += sacc[i];
            atomicAdd(&g_acc[z], (double)t);
        }
    }
}

// ---------------------------------------------------------------------------
__global__ void final_kernel(float* __restrict__ out)
{
    const int t = threadIdx.x;
    float v = 0.f;
    if (t < NIMG) {
        double tp = g_acc[t], ts = g_acc[NIMG + t];
        double num = 2.0 * tp * ts;
        double den = tp + ts;
        double c = (den > 0.0) ? (num + 1e-6) / (den + 1e-6) : 1.0;
        c = fmin(fmax(c, 0.0), 1.0);
        v = (float)(1.0 - c);
    }
    for (int o = 16; o > 0; o >>= 1) v += __shfl_down_sync(0xffffffffu, v, o);
    if (t == 0) out[0] = v / (float)NIMG;
}

// ---------------------------------------------------------------------------
extern "C" void kernel_launch(void* const* d_in, const int* in_sizes, int n_in,
                              void* d_out, int out_size)
{
    const float* logits = (const float*)d_in[0];
    const int*   target = (const int*)d_in[1];
    float*       out    = (float*)d_out;

    float *A = nullptr, *B = nullptr;
    cudaGetSymbolAddress((void**)&A, g_bufA);
    cudaGetSymbolAddress((void**)&B, g_bufB);

    dim3 grid(CTILES, IMG_H / (R * NWARP), NF);   // 37 x 8 x 32
    const int blk = NWARP * 32;

    skel_kernel<0><<<grid, blk>>>(nullptr, logits, target, A);  // iter 1 (fused sigmoid)
    skel_kernel<1><<<grid, blk>>>(A, nullptr, nullptr, B);      // iter 2
    skel_kernel<1><<<grid, blk>>>(B, nullptr, nullptr, A);      // iter 3
    skel_kernel<1><<<grid, blk>>>(A, nullptr, nullptr, B);      // iter 4
    skel_kernel<2><<<grid, blk>>>(B, logits, target, nullptr);  // iter 5 + reduce
    final_kernel<<<1, 32>>>(out);
}

// round 4
// speedup vs baseline: 3.5608x; 1.0677x over previous
#include <cuda_runtime.h>
#include <math_constants.h>

#define IMG_H 1024
#define IMG_W 1024
#define IMG   (IMG_H * IMG_W)
#define NIMG  16
#define NF    32            // [0..15]=pred(sigmoid(logits)), [16..31]=gt(target)
#define TCOLS 128           // columns per warp tile (32 lanes x float4)
#define R     32            // output rows per warp
#define NWARP 4
#define FINF  CUDART_INF_F

__device__ float  g_bufA[(size_t)NF * IMG];   // 128 MB scratch
__device__ float  g_bufB[(size_t)NF * IMG];   // 128 MB scratch
__device__ double g_acc[NF];                  // [0..15]=tp, [16..31]=ts

__device__ __forceinline__ float sigmoidf(float x) { return 1.f / (1.f + __expf(-x)); }
__device__ __forceinline__ float4 sigmoid4(float4 l) {
    return make_float4(sigmoidf(l.x), sigmoidf(l.y), sigmoidf(l.z), sigmoidf(l.w));
}
__device__ __forceinline__ float4 min3v(float4 a, float4 b, float4 c) {
    return make_float4(fminf(a.x, fminf(b.x, c.x)), fminf(a.y, fminf(b.y, c.y)),
                       fminf(a.z, fminf(b.z, c.z)), fminf(a.w, fminf(b.w, c.w)));
}
__device__ __forceinline__ float4 max3v(float4 a, float4 b, float4 c) {
    return make_float4(fmaxf(a.x, fmaxf(b.x, c.x)), fmaxf(a.y, fmaxf(b.y, c.y)),
                       fmaxf(a.z, fmaxf(b.z, c.z)), fmaxf(a.w, fmaxf(b.w, c.w)));
}

// ---------------------------------------------------------------------------
// One soft-skeleton iteration: rolling-register separable min/max pools,
// float4 per lane (128 cols per warp), 3-row pipelines, 2 shuffles per row.
// MODE 0: x = sigmoid(logits) / (float)target  (fused init) -> dst
// MODE 1: src -> dst
// MODE 2: no store; accumulate tp/ts (fused reduction epilogue)
// ---------------------------------------------------------------------------
template<int MODE>
__global__ void __launch_bounds__(NWARP * 32)
skel_kernel(const float* __restrict__ src,
            const float* __restrict__ logits,
            const int*   __restrict__ target,
            float*       __restrict__ dst)
{
    const int lane  = threadIdx.x & 31;
    const int warp  = threadIdx.x >> 5;
    const int z     = blockIdx.z;
    const int tile0 = blockIdx.x * TCOLS;
    const int cbase = tile0 + lane * 4;
    const int row0  = (blockIdx.y * NWARP + warp) * R;
    const bool isL  = (lane == 0), isR = (lane == 31);
    const bool leftIn  = (blockIdx.x != 0);
    const bool rightIn = (blockIdx.x != gridDim.x - 1);
    const bool hlAct = isL && leftIn;
    const bool hrAct = isR && rightIn;
    const int  hlc0 = tile0 - 2, hrc0 = tile0 + TCOLS;

    if (MODE == 0 && blockIdx.x == 0 && blockIdx.y == 0 && blockIdx.z == 0 &&
        threadIdx.x < NF)
        g_acc[threadIdx.x] = 0.0;   // runs before MODE 2 (stream-ordered)

    const int img = (z < NIMG) ? z : z - NIMG;
    const float* __restrict__ lg = logits + (size_t)img * IMG;
    const int*   __restrict__ tg = target + (size_t)img * IMG;
    const float* __restrict__ sp = (MODE != 0) ? src + (size_t)z * IMG : nullptr;
    float* __restrict__ dp = (MODE != 2) ? dst + (size_t)z * IMG : nullptr;

    auto ldrow = [&](int r) -> float4 {
        if ((unsigned)r >= IMG_H) return make_float4(FINF, FINF, FINF, FINF);
        size_t off = (size_t)r * IMG_W + cbase;
        if (MODE == 0) {
            if (z < NIMG) return sigmoid4(__ldg((const float4*)(lg + off)));
            int4 t = __ldg((const int4*)(tg + off));
            return make_float4((float)t.x, (float)t.y, (float)t.z, (float)t.w);
        }
        return __ldg((const float4*)(sp + off));
    };
    auto ldh = [&](int r, int c, bool act) -> float2 {  // cols c, c+1
        if (!act || (unsigned)r >= IMG_H) return make_float2(FINF, FINF);
        size_t off = (size_t)r * IMG_W + c;
        if (MODE == 0) {
            if (z < NIMG) {
                float2 l = __ldg((const float2*)(lg + off));
                return make_float2(sigmoidf(l.x), sigmoidf(l.y));
            }
            int2 t = __ldg((const int2*)(tg + off));
            return make_float2((float)t.x, (float)t.y);
        }
        return __ldg((const float2*)(sp + off));
    };

    // 3-row rolling pipelines
    float4 xa = ldrow(row0 - 2), xb = ldrow(row0 - 1);
    float2 hla = ldh(row0 - 2, hlc0, hlAct), hlb = ldh(row0 - 1, hlc0, hlAct);
    float2 hra = ldh(row0 - 2, hrc0, hrAct), hrb = ldh(row0 - 1, hrc0, hrAct);
    float4 er2 = {}, er1 = {};
    float erl2 = 0.f, erl1 = 0.f, errv2 = 0.f, errv1 = 0.f;
    float accum = 0.f;

    #pragma unroll 2
    for (int k = row0 - 1; k <= row0 + R; ++k) {
        float4 xc  = ldrow(k + 1);
        float2 hlc = ldh(k + 1, hlc0, hlAct);
        float2 hrc = ldh(k + 1, hrc0, hrAct);

        // vertical min3 (rows k-1..k+1)
        float4 v = min3v(xa, xb, xc);
        float2 vl = make_float2(fminf(hla.x, fminf(hlb.x, hlc.x)),
                                fminf(hla.y, fminf(hlb.y, hlc.y)));
        float2 vr = make_float2(fminf(hra.x, fminf(hrb.x, hrc.x)),
                                fminf(hra.y, fminf(hrb.y, hrc.y)));

        // horizontal min3 -> eroded row k
        float vleft  = __shfl_up_sync(0xffffffffu, v.w, 1);
        if (isL) vleft = vl.y;
        float vright = __shfl_down_sync(0xffffffffu, v.x, 1);
        if (isR) vright = vr.x;
        float4 er;
        er.x = fminf(vleft, fminf(v.x, v.y));
        er.y = fminf(v.x,   fminf(v.y, v.z));
        er.z = fminf(v.y,   fminf(v.z, v.w));
        er.w = fminf(v.z,   fminf(v.w, vright));
        float erl  = leftIn  ? fminf(vl.x, fminf(vl.y, v.x)) : -FINF;  // col tile0-1
        float errv = rightIn ? fminf(v.w, fminf(vr.x, vr.y)) : -FINF;  // col tile0+128
        if ((unsigned)k >= IMG_H) {       // out-of-image eroded row -> -inf pad
            er = make_float4(-FINF, -FINF, -FINF, -FINF);
            erl = -FINF; errv = -FINF;
        }

        if (k >= row0 + 1) {              // emit output row k-1 (x row = xa)
            float4 m = max3v(er2, er1, er);
            float mleft  = __shfl_up_sync(0xffffffffu, m.w, 1);
            if (isL) mleft = fmaxf(erl2, fmaxf(erl1, erl));
            float mright = __shfl_down_sync(0xffffffffu, m.x, 1);
            if (isR) mright = fmaxf(errv2, fmaxf(errv1, errv));
            float4 op;
            op.x = fmaxf(mleft, fmaxf(m.x, m.y));
            op.y = fmaxf(m.x,   fmaxf(m.y, m.z));
            op.z = fmaxf(m.y,   fmaxf(m.z, m.w));
            op.w = fmaxf(m.z,   fmaxf(m.w, mright));
            float4 nx;
            nx.x = fminf(fmaxf(xa.x - (op.x - er1.x), 0.f), 1.f);
            nx.y = fminf(fmaxf(xa.y - (op.y - er1.y), 0.f), 1.f);
            nx.z = fminf(fmaxf(xa.z - (op.z - er1.z), 0.f), 1.f);
            nx.w = fminf(fmaxf(xa.w - (op.w - er1.w), 0.f), 1.f);

            if (MODE == 2) {
                size_t off = (size_t)(k - 1) * IMG_W + cbase;
                float4 w;
                if (z < NIMG) {               // tp: skel_pred * target
                    int4 t = __ldg((const int4*)(tg + off));
                    w = make_float4((float)t.x, (float)t.y, (float)t.z, (float)t.w);
                } else {                      // ts: skel_gt * sigmoid(logits)
                    w = sigmoid4(__ldg((const float4*)(lg + off)));
                }
                accum += nx.x * w.x + nx.y * w.y + nx.z * w.z + nx.w * w.w;
            } else {
                *(float4*)(dp + (size_t)(k - 1) * IMG_W + cbase) = nx;
            }
        }

        er2 = er1; er1 = er;
        erl2 = erl1; erl1 = erl; errv2 = errv1; errv1 = errv;
        xa = xb; xb = xc;
        hla = hlb; hlb = hlc;
        hra = hrb; hrb = hrc;
    }

    if (MODE == 2) {
        #pragma unroll
        for (int o = 16; o > 0; o >>= 1)
            accum += __shfl_down_sync(0xffffffffu, accum, o);
        __shared__ float sacc[NWARP];
        if (lane == 0) sacc[warp] = accum;
        __syncthreads();
        if (threadIdx.x == 0) {
            float t = 0.f;
            #pragma unroll
            for (int i = 0; i < NWARP; ++i) t += sacc[i];
            atomicAdd(&g_acc[z], (double)t);
        }
    }
}

// ---------------------------------------------------------------------------
__global__ void final_kernel(float* __restrict__ out)
{
    const int t = threadIdx.x;
    float v = 0.f;
    if (t < NIMG) {
        double tp = g_acc[t], ts = g_acc[NIMG + t];
        double num = 2.0 * tp * ts;
        double den = tp + ts;
        double c = (den > 0.0) ? (num + 1e-6) / (den + 1e-6) : 1.0;
        c = fmin(fmax(c, 0.0), 1.0);
        v = (float)(1.0 - c);
    }
    for (int o = 16; o > 0; o >>= 1) v += __shfl_down_sync(0xffffffffu, v, o);
    if (t == 0) out[0] = v / (float)NIMG;
}

// ---------------------------------------------------------------------------
extern "C" void kernel_launch(void* const* d_in, const int* in_sizes, int n_in,
                              void* d_out, int out_size)
{
    const float* logits = (const float*)d_in[0];
    const int*   target = (const int*)d_in[1];
    float*       out    = (float*)d_out;

    float *A = nullptr, *B = nullptr;
    cudaGetSymbolAddress((void**)&A, g_bufA);
    cudaGetSymbolAddress((void**)&B, g_bufB);

    dim3 grid(IMG_W / TCOLS, IMG_H / (R * NWARP), NF);   // 8 x 8 x 32
    const int blk = NWARP * 32;

    skel_kernel<0><<<grid, blk>>>(nullptr, logits, target, A);  // iter 1 + sigmoid
    skel_kernel<1><<<grid, blk>>>(A, nullptr, nullptr, B);      // iter 2
    skel_kernel<1><<<grid, blk>>>(B, nullptr, nullptr, A);      // iter 3
    skel_kernel<1><<<grid, blk>>>(A, nullptr, nullptr, B);      // iter 4
    skel_kernel<2><<<grid, blk>>>(B, logits, target, nullptr);  // iter 5 + reduce
    final_kernel<<<1, 32>>>(out);
}

// round 5
// speedup vs baseline: 4.4722x; 1.2559x over previous
#include <cuda_runtime.h>
#include <math_constants.h>

#define IMG_H 1024
#define IMG_W 1024
#define IMG   (IMG_H * IMG_W)
#define NIMG  16
#define NF    32            // [0..15]=pred(sigmoid(logits)), [16..31]=gt(target)
#define OUTC  120           // output cols per warp (128-col window, 4-col halo each side)
#define XT    9             // ceil(1024/120)
#define R     32            // output rows per warp
#define NWARP 4
#define FINF  CUDART_INF_F

__device__ float  g_bufA[(size_t)NF * IMG];   // 128 MB scratch
__device__ float  g_bufB[(size_t)NF * IMG];   // 128 MB scratch
__device__ double g_acc[NF];                  // [0..15]=tp, [16..31]=ts

__device__ __forceinline__ float sigmoidf(float x) { return 1.f / (1.f + __expf(-x)); }
__device__ __forceinline__ float4 vmin3(float4 a, float4 b, float4 c) {
    return make_float4(fminf(a.x, fminf(b.x, c.x)), fminf(a.y, fminf(b.y, c.y)),
                       fminf(a.z, fminf(b.z, c.z)), fminf(a.w, fminf(b.w, c.w)));
}
__device__ __forceinline__ float4 vmax3(float4 a, float4 b, float4 c) {
    return make_float4(fmaxf(a.x, fmaxf(b.x, c.x)), fmaxf(a.y, fmaxf(b.y, c.y)),
                       fmaxf(a.z, fmaxf(b.z, c.z)), fmaxf(a.w, fmaxf(b.w, c.w)));
}
__device__ __forceinline__ float4 hmin(float4 v) {
    float l = __shfl_up_sync(0xffffffffu, v.w, 1);
    float r = __shfl_down_sync(0xffffffffu, v.x, 1);
    return make_float4(fminf(l,   fminf(v.x, v.y)),
                       fminf(v.x, fminf(v.y, v.z)),
                       fminf(v.y, fminf(v.z, v.w)),
                       fminf(v.z, fminf(v.w, r)));
}
__device__ __forceinline__ float4 hmax(float4 v) {
    float l = __shfl_up_sync(0xffffffffu, v.w, 1);
    float r = __shfl_down_sync(0xffffffffu, v.x, 1);
    return make_float4(fmaxf(l,   fmaxf(v.x, v.y)),
                       fmaxf(v.x, fmaxf(v.y, v.z)),
                       fmaxf(v.y, fmaxf(v.z, v.w)),
                       fmaxf(v.z, fmaxf(v.w, r)));
}
__device__ __forceinline__ float4 upd(float4 x, float4 op, float4 er) {
    return make_float4(__saturatef(x.x - (op.x - er.x)),
                       __saturatef(x.y - (op.y - er.y)),
                       __saturatef(x.z - (op.z - er.z)),
                       __saturatef(x.w - (op.w - er.w)));
}

// ---------------------------------------------------------------------------
// MODE 0: x = sigmoid(logits)/(float)target; 2 skeleton iterations; store.
// MODE 1: load buffer; 2 skeleton iterations; store.
// MODE 2: load buffer; 1 skeleton iteration; accumulate tp/ts (no store).
// Each warp: 128-col window (lane*4), emits inner 120 cols; rolling row
// pipeline with lag 4 (x -> er1 -> x' -> er2 -> x''); 2 shuffles/stage/row.
// ---------------------------------------------------------------------------
template<int MODE>
__global__ void __launch_bounds__(NWARP * 32)
skel_kernel(const float* __restrict__ src,
            const float* __restrict__ logits,
            const int*   __restrict__ target,
            float*       __restrict__ dst)
{
    const int lane = threadIdx.x & 31;
    const int warp = threadIdx.x >> 5;
    const int z    = blockIdx.z;
    const int c0   = blockIdx.x * OUTC - 4 + lane * 4;
    const int row0 = (blockIdx.y * NWARP + warp) * R;
    const bool v0 = (unsigned)c0       < IMG_W;
    const bool v1 = (unsigned)(c0 + 1) < IMG_W;
    const bool v2 = (unsigned)(c0 + 2) < IMG_W;
    const bool v3 = (unsigned)(c0 + 3) < IMG_W;
    const bool allv = (c0 >= 0) && (c0 + 3 < IMG_W);

    if (MODE == 0 && blockIdx.x == 0 && blockIdx.y == 0 && blockIdx.z == 0 &&
        threadIdx.x < NF)
        g_acc[threadIdx.x] = 0.0;   // stream-ordered before MODE 2

    const int img = (z < NIMG) ? z : z - NIMG;
    const float* __restrict__ lg = logits + (size_t)img * IMG;
    const int*   __restrict__ tg = target + (size_t)img * IMG;
    const float* __restrict__ sp = (MODE != 0) ? src + (size_t)z * IMG : nullptr;
    float* __restrict__ dp = (MODE != 2) ? dst + (size_t)z * IMG : nullptr;

    const float4 P4 = make_float4( FINF,  FINF,  FINF,  FINF);
    const float4 N4 = make_float4(-FINF, -FINF, -FINF, -FINF);

    auto ld1 = [&](long long idx, bool v) -> float {
        if (!v) return FINF;
        if (MODE == 0)
            return (z < NIMG) ? sigmoidf(__ldg(lg + idx)) : (float)__ldg(tg + idx);
        return __ldg(sp + idx);
    };
    auto ldrow = [&](int r) -> float4 {
        if ((unsigned)r >= IMG_H) return P4;
        long long rb = (long long)r * IMG_W;
        if (allv) {
            if (MODE == 0) {
                if (z < NIMG) {
                    float4 l = __ldg((const float4*)(lg + rb + c0));
                    return make_float4(sigmoidf(l.x), sigmoidf(l.y),
                                       sigmoidf(l.z), sigmoidf(l.w));
                }
                int4 t = __ldg((const int4*)(tg + rb + c0));
                return make_float4((float)t.x, (float)t.y, (float)t.z, (float)t.w);
            }
            return __ldg((const float4*)(sp + rb + c0));
        }
        return make_float4(ld1(rb + c0, v0), ld1(rb + c0 + 1, v1),
                           ld1(rb + c0 + 2, v2), ld1(rb + c0 + 3, v3));
    };
    auto cmaskN = [&](float4 e) -> float4 {        // invalid global col -> -inf
        if (allv) return e;
        return make_float4(v0 ? e.x : -FINF, v1 ? e.y : -FINF,
                           v2 ? e.z : -FINF, v3 ? e.w : -FINF);
    };
    auto cmaskP = [&](float4 e) -> float4 {        // invalid global col -> +inf
        if (allv) return e;
        return make_float4(v0 ? e.x : FINF, v1 ? e.y : FINF,
                           v2 ? e.z : FINF, v3 ? e.w : FINF);
    };
    const bool emitLane = (lane >= 1) && (lane <= 30);
    float accum = 0.f;

    if (MODE != 2) {
        // ---- two fused skeleton iterations ----
        float4 xa = ldrow(row0 - 4), xb = ldrow(row0 - 3);
        float4 e1a = {}, e1b = {}, pa = {}, pb = {}, qa = {}, qb = {};
        #pragma unroll 2
        for (int k = row0 - 3; k <= row0 + R + 2; ++k) {
            float4 xc = ldrow(k + 1);
            // er1 row k
            float4 e1 = ((unsigned)k < IMG_H) ? cmaskN(hmin(vmin3(xa, xb, xc))) : N4;
            // x' row k-1
            float4 op1 = hmax(vmax3(e1a, e1b, e1));
            float4 xp  = ((unsigned)(k - 1) < IMG_H) ? cmaskP(upd(xa, op1, e1b)) : P4;
            // er2 row k-2
            float4 e2 = ((unsigned)(k - 2) < IMG_H) ? cmaskN(hmin(vmin3(pa, pb, xp))) : N4;
            // emit x'' row k-3
            if (k >= row0 + 3) {
                float4 op2 = hmax(vmax3(qa, qb, e2));
                float4 nx  = upd(pa, op2, qb);
                if (emitLane) {
                    long long ob = (long long)(k - 3) * IMG_W + c0;
                    if (c0 + 3 < IMG_W) {
                        *(float4*)(dp + ob) = nx;
                    } else {
                        if (v0) dp[ob]     = nx.x;
                        if (v1) dp[ob + 1] = nx.y;
                        if (v2) dp[ob + 2] = nx.z;
                        if (v3) dp[ob + 3] = nx.w;
                    }
                }
            }
            qa = qb; qb = e2; pa = pb; pb = xp;
            e1a = e1b; e1b = e1; xa = xb; xb = xc;
        }
    } else {
        // ---- final skeleton iteration + reduction ----
        float4 xa = ldrow(row0 - 2), xb = ldrow(row0 - 1);
        float4 e1a = {}, e1b = {};
        #pragma unroll 2
        for (int k = row0 - 1; k <= row0 + R; ++k) {
            float4 xc = ldrow(k + 1);
            float4 e1 = ((unsigned)k < IMG_H) ? cmaskN(hmin(vmin3(xa, xb, xc))) : N4;
            if (k >= row0 + 1) {
                float4 op = hmax(vmax3(e1a, e1b, e1));
                float4 nx = upd(xa, op, e1b);          // row k-1, saturated finite
                if (emitLane) {
                    long long ob = (long long)(k - 1) * IMG_W + c0;
                    float4 w = make_float4(0.f, 0.f, 0.f, 0.f);
                    if (z < NIMG) {                    // tp: skel_pred * target
                        if (allv) {
                            int4 t = __ldg((const int4*)(tg + ob));
                            w = make_float4((float)t.x, (float)t.y, (float)t.z, (float)t.w);
                        } else {
                            if (v0) w.x = (float)__ldg(tg + ob);
                            if (v1) w.y = (float)__ldg(tg + ob + 1);
                            if (v2) w.z = (float)__ldg(tg + ob + 2);
                            if (v3) w.w = (float)__ldg(tg + ob + 3);
                        }
                    } else {                           // ts: skel_gt * sigmoid(logits)
                        if (allv) {
                            float4 l = __ldg((const float4*)(lg + ob));
                            w = make_float4(sigmoidf(l.x), sigmoidf(l.y),
                                            sigmoidf(l.z), sigmoidf(l.w));
                        } else {
                            if (v0) w.x = sigmoidf(__ldg(lg + ob));
                            if (v1) w.y = sigmoidf(__ldg(lg + ob + 1));
                            if (v2) w.z = sigmoidf(__ldg(lg + ob + 2));
                            if (v3) w.w = sigmoidf(__ldg(lg + ob + 3));
                        }
                    }
                    accum += nx.x * w.x + nx.y * w.y + nx.z * w.z + nx.w * w.w;
                }
            }
            e1a = e1b; e1b = e1; xa = xb; xb = xc;
        }
        #pragma unroll
        for (int o = 16; o > 0; o >>= 1)
            accum += __shfl_down_sync(0xffffffffu, accum, o);
        __shared__ float sacc[NWARP];
        if (lane == 0) sacc[warp] = accum;
        __syncthreads();
        if (threadIdx.x == 0) {
            float t = 0.f;
            #pragma unroll
            for (int i = 0; i < NWARP; ++i) t += sacc[i];
            atomicAdd(&g_acc[z], (double)t);
        }
    }
}

// ---------------------------------------------------------------------------
__global__ void final_kernel(float* __restrict__ out)
{
    const int t = threadIdx.x;
    float v = 0.f;
    if (t < NIMG) {
        double tp = g_acc[t], ts = g_acc[NIMG + t];
        double num = 2.0 * tp * ts;
        double den = tp + ts;
        double c = (den > 0.0) ? (num + 1e-6) / (den + 1e-6) : 1.0;
        c = fmin(fmax(c, 0.0), 1.0);
        v = (float)(1.0 - c);
    }
    for (int o = 16; o > 0; o >>= 1) v += __shfl_down_sync(0xffffffffu, v, o);
    if (t == 0) out[0] = v / (float)NIMG;
}

// ---------------------------------------------------------------------------
extern "C" void kernel_launch(void* const* d_in, const int* in_sizes, int n_in,
                              void* d_out, int out_size)
{
    const float* logits = (const float*)d_in[0];
    const int*   target = (const int*)d_in[1];
    float*       out    = (float*)d_out;

    float *A = nullptr, *B = nullptr;
    cudaGetSymbolAddress((void**)&A, g_bufA);
    cudaGetSymbolAddress((void**)&B, g_bufB);

    dim3 grid(XT, IMG_H / (R * NWARP), NF);   // 9 x 8 x 32
    const int blk = NWARP * 32;

    skel_kernel<0><<<grid, blk>>>(nullptr, logits, target, A);  // sigmoid + iters 1-2
    skel_kernel<1><<<grid, blk>>>(A, nullptr, nullptr, B);      // iters 3-4
    skel_kernel<2><<<grid, blk>>>(B, logits, target, nullptr);  // iter 5 + reduce
    final_kernel<<<1, 32>>>(out);
}